// round 3
// baseline (speedup 1.0000x reference)
#include <cuda_runtime.h>
#include <math.h>

#define BB 8
#define NN 8192
#define SS 1024
#define KK 64

// output layout (float32): new_xyz (B,3,S) | new_points (B,128,S) | new_seed (B,S)
#define OUT_XYZ_OFF   0
#define OUT_PTS_OFF   (BB*3*SS)                 // 24576
#define OUT_SEED_OFF  (OUT_PTS_OFF + BB*128*SS) // 1073152

// ---------------- scratch (no allocations allowed) ----------------
__device__ float g_cent[BB*SS*3];
__device__ int   g_gi[BB*SS*KK];
__device__ int   g_cnt[BB*SS];
__device__ float g_w0[64*6],  g_b0[64];
__device__ float g_w1[64*64], g_b1[64];
__device__ float g_w2[128*64], g_b2[128];

// ---------------- fold BN into weights ----------------
__global__ void fold_kernel(
    const float* __restrict__ w0, const float* __restrict__ b0, const float* __restrict__ g0,
    const float* __restrict__ be0, const float* __restrict__ m0, const float* __restrict__ v0,
    const float* __restrict__ w1, const float* __restrict__ b1, const float* __restrict__ g1,
    const float* __restrict__ be1, const float* __restrict__ m1, const float* __restrict__ v1,
    const float* __restrict__ w2, const float* __restrict__ b2, const float* __restrict__ g2,
    const float* __restrict__ be2, const float* __restrict__ m2, const float* __restrict__ v2)
{
    int t = threadIdx.x;
    if (t < 64) {
        float s = g0[t] / sqrtf(v0[t] + 1e-5f);
        g_b0[t] = (b0[t] - m0[t]) * s + be0[t];
        for (int c = 0; c < 6; c++) g_w0[t*6+c] = w0[t*6+c] * s;
    }
    if (t < 64) {
        float s = g1[t] / sqrtf(v1[t] + 1e-5f);
        g_b1[t] = (b1[t] - m1[t]) * s + be1[t];
        for (int c = 0; c < 64; c++) g_w1[t*64+c] = w1[t*64+c] * s;
    }
    if (t < 128) {
        float s = g2[t] / sqrtf(v2[t] + 1e-5f);
        g_b2[t] = (b2[t] - m2[t]) * s + be2[t];
        for (int c = 0; c < 64; c++) g_w2[t*64+c] = w2[t*64+c] * s;
    }
}

// ---------------- FPS: one block per batch ----------------
// Distances computed WITHOUT fma, in the reference association order:
// ((dx*dx + dy*dy) + dz*dz), to match XLA CPU bit-for-bit (selection-critical).
__global__ __launch_bounds__(1024) void fps_kernel(
    const float* __restrict__ xyz, const int* __restrict__ seed, float* __restrict__ out)
{
    const int b = blockIdx.x;
    const float* xr = xyz + (size_t)b*3*NN;
    const float* yr = xr + NN;
    const float* zr = yr + NN;
    const int tid = threadIdx.x, lane = tid & 31, warp = tid >> 5;
    const int base = tid * 8;

    float px[8], py[8], pz[8], dist[8];
#pragma unroll
    for (int i = 0; i < 8; i++) {
        px[i] = xr[base+i]; py[i] = yr[base+i]; pz[i] = zr[base+i];
        dist[i] = 1e10f;
    }

    __shared__ float sval[32];
    __shared__ int   sidx[32];
    __shared__ int   sfar;
    __shared__ int   sfps[SS];

    int far = 0;
    for (int s = 0; s < SS; s++) {
        if (tid == 0) sfps[s] = far;
        if (s == SS - 1) break;

        float cx = xr[far], cy = yr[far], cz = zr[far];
        float bv = -1.0f; int bi = 0;
#pragma unroll
        for (int i = 0; i < 8; i++) {
            float dx = px[i] - cx, dy = py[i] - cy, dz = pz[i] - cz;
            float d = __fadd_rn(__fadd_rn(__fmul_rn(dx,dx), __fmul_rn(dy,dy)), __fmul_rn(dz,dz));
            float nd = fminf(dist[i], d);
            dist[i] = nd;
            if (nd > bv) { bv = nd; bi = base + i; }
        }
        // warp argmax (ties -> lowest index, matching jnp.argmax)
#pragma unroll
        for (int off = 16; off; off >>= 1) {
            float v2 = __shfl_down_sync(0xffffffffu, bv, off);
            int   i2 = __shfl_down_sync(0xffffffffu, bi, off);
            if (v2 > bv || (v2 == bv && i2 < bi)) { bv = v2; bi = i2; }
        }
        if (lane == 0) { sval[warp] = bv; sidx[warp] = bi; }
        __syncthreads();
        if (warp == 0) {
            bv = sval[lane]; bi = sidx[lane];
#pragma unroll
            for (int off = 16; off; off >>= 1) {
                float v2 = __shfl_down_sync(0xffffffffu, bv, off);
                int   i2 = __shfl_down_sync(0xffffffffu, bi, off);
                if (v2 > bv || (v2 == bv && i2 < bi)) { bv = v2; bi = i2; }
            }
            if (lane == 0) sfar = bi;
        }
        __syncthreads();
        far = sfar;
    }
    __syncthreads();

    // outputs: new_xyz (B,3,S), new_seed (B,S), centroid scratch
    {
        int id = sfps[tid];
        float x = xr[id], y = yr[id], z = zr[id];
        out[OUT_XYZ_OFF + (size_t)b*3*SS + 0*SS + tid] = x;
        out[OUT_XYZ_OFF + (size_t)b*3*SS + 1*SS + tid] = y;
        out[OUT_XYZ_OFF + (size_t)b*3*SS + 2*SS + tid] = z;
        out[OUT_SEED_OFF + (size_t)b*SS + tid] = (float)seed[(size_t)b*NN + id];
        g_cent[((size_t)b*SS + tid)*3 + 0] = x;
        g_cent[((size_t)b*SS + tid)*3 + 1] = y;
        g_cent[((size_t)b*SS + tid)*3 + 2] = z;
    }
}

// ---------------- ball query: warp per centroid ----------------
// sq dist uses the reference formula (-2*dot + |src|^2 + |dst|^2) without fma.
__global__ __launch_bounds__(256) void ballq_kernel(const float* __restrict__ xyz)
{
    const int gw = blockIdx.x * 8 + (threadIdx.x >> 5);
    const int lane = threadIdx.x & 31;
    const int b = gw >> 10;
    const int s = gw & 1023;
    const float* xr = xyz + (size_t)b*3*NN;
    const float* yr = xr + NN;
    const float* zr = yr + NN;

    const float cx = g_cent[((size_t)b*SS+s)*3+0];
    const float cy = g_cent[((size_t)b*SS+s)*3+1];
    const float cz = g_cent[((size_t)b*SS+s)*3+2];
    const float s2 = __fadd_rn(__fadd_rn(__fmul_rn(cx,cx), __fmul_rn(cy,cy)), __fmul_rn(cz,cz));

    __shared__ int sgi[8][KK];
    int* mygi = sgi[threadIdx.x >> 5];

    int cnt = 0;
    for (int j0 = 0; j0 < NN; j0 += 32) {
        int j = j0 + lane;
        float x = xr[j], y = yr[j], z = zr[j];
        float d2  = __fadd_rn(__fadd_rn(__fmul_rn(x,x), __fmul_rn(y,y)), __fmul_rn(z,z));
        float dot = __fadd_rn(__fadd_rn(__fmul_rn(cx,x), __fmul_rn(cy,y)), __fmul_rn(cz,z));
        float sq  = __fadd_rn(__fadd_rn(__fmul_rn(-2.0f, dot), s2), d2);
        bool pred = !(sq > 0.04f);
        unsigned m = __ballot_sync(0xffffffffu, pred);
        int rank = __popc(m & ((1u << lane) - 1u));
        if (pred && (cnt + rank) < KK) mygi[cnt + rank] = j;
        cnt += __popc(m);
        if (cnt >= KK) { cnt = KK; break; }
    }
    __syncwarp();
    int first = mygi[0];
    for (int k = cnt + lane; k < KK; k += 32) mygi[k] = first;
    __syncwarp();
    if (lane == 0) g_cnt[(size_t)b*SS + s] = cnt;
    for (int k = lane; k < KK; k += 32)
        g_gi[((size_t)b*SS + s)*KK + k] = mygi[k];
}

// ---------------- fused gather + 3-layer MLP + maxpool ----------------
// 256 threads = 4 centroids x 64 neighbors. Weights in dynamic shared.
// Threads with k >= cnt (reference padding duplicates) skip all compute.
#define SW0_OFF 0
#define SB0_OFF 384
#define SW1_OFF 448
#define SB1_OFF 4544
#define SW2_OFF 4608
#define SB2_OFF 12800
#define SMAX_OFF 12928
#define SMEM_FLOATS (SMAX_OFF + 4*128)

__global__ __launch_bounds__(256) void mlp_kernel(
    const float* __restrict__ xyz, const float* __restrict__ pts, float* __restrict__ out)
{
    extern __shared__ float smem[];
    float* sw0 = smem + SW0_OFF;
    float* sb0 = smem + SB0_OFF;
    float* sw1 = smem + SW1_OFF;
    float* sb1 = smem + SB1_OFF;
    float* sw2 = smem + SW2_OFF;
    float* sb2 = smem + SB2_OFF;
    float* sMax = smem + SMAX_OFF;

    const int tid = threadIdx.x;
    for (int i = tid; i < 384;  i += 256) sw0[i] = g_w0[i];
    for (int i = tid; i < 64;   i += 256) { sb0[i] = g_b0[i]; sb1[i] = g_b1[i]; }
    for (int i = tid; i < 4096; i += 256) sw1[i] = g_w1[i];
    for (int i = tid; i < 8192; i += 256) sw2[i] = g_w2[i];
    for (int i = tid; i < 128;  i += 256) sb2[i] = g_b2[i];
    for (int i = tid; i < 512;  i += 256) sMax[i] = 0.0f;
    __syncthreads();

    const int ci = tid >> 6;
    const int k  = tid & 63;
    const int lane = tid & 31;
    const int b = blockIdx.x >> 8;
    const int s = (blockIdx.x & 255) * 4 + ci;

    const int cnt = g_cnt[(size_t)b*SS + s];
    const bool act = (k < cnt);

    float h2[64];
    if (act) {
        const float cx = g_cent[((size_t)b*SS+s)*3+0];
        const float cy = g_cent[((size_t)b*SS+s)*3+1];
        const float cz = g_cent[((size_t)b*SS+s)*3+2];
        const int idx = g_gi[((size_t)b*SS + s)*KK + k];
        const float* xr = xyz + (size_t)b*3*NN;
        const float* pr = pts + (size_t)b*3*NN;
        float f0 = xr[idx] - cx;
        float f1 = xr[NN + idx] - cy;
        float f2 = xr[2*NN + idx] - cz;
        float f3 = pr[idx];
        float f4 = pr[NN + idx];
        float f5 = pr[2*NN + idx];

        float h1[64];
#pragma unroll
        for (int j = 0; j < 64; j++) {
            const float* w = sw0 + j*6;
            float a = sb0[j] + w[0]*f0 + w[1]*f1 + w[2]*f2 + w[3]*f3 + w[4]*f4 + w[5]*f5;
            h1[j] = fmaxf(a, 0.0f);
        }
        const float4* w1v = (const float4*)sw1;
#pragma unroll
        for (int j = 0; j < 64; j++) {
            float a = sb1[j];
#pragma unroll
            for (int c = 0; c < 16; c++) {
                float4 w = w1v[j*16 + c];
                a += w.x*h1[4*c] + w.y*h1[4*c+1] + w.z*h1[4*c+2] + w.w*h1[4*c+3];
            }
            h2[j] = fmaxf(a, 0.0f);
        }
    }

    const float4* w2v = (const float4*)sw2;
#pragma unroll 2
    for (int o = 0; o < 128; o++) {
        float v = 0.0f;
        if (act) {
            float a = sb2[o];
#pragma unroll
            for (int c = 0; c < 16; c++) {
                float4 w = w2v[o*16 + c];
                a += w.x*h2[4*c] + w.y*h2[4*c+1] + w.z*h2[4*c+2] + w.w*h2[4*c+3];
            }
            v = fmaxf(a, 0.0f);
        }
#pragma unroll
        for (int off = 16; off; off >>= 1)
            v = fmaxf(v, __shfl_down_sync(0xffffffffu, v, off));
        if (lane == 0)
            atomicMax((int*)&sMax[ci*128 + o], __float_as_int(v));
    }
    __syncthreads();

    for (int i = tid; i < 512; i += 256) {
        int cc = i >> 7, o = i & 127;
        int so = (blockIdx.x & 255) * 4 + cc;
        out[OUT_PTS_OFF + ((size_t)b*128 + o)*SS + so] = sMax[cc*128 + o];
    }
}

// ---------------- launch ----------------
extern "C" void kernel_launch(void* const* d_in, const int* in_sizes, int n_in,
                              void* d_out, int out_size)
{
    const float* xyz  = (const float*)d_in[0];
    const float* pts  = (const float*)d_in[1];
    const int*   seed = (const int*)d_in[2];
    float* out = (float*)d_out;

    fold_kernel<<<1, 128>>>(
        (const float*)d_in[3],  (const float*)d_in[4],  (const float*)d_in[5],
        (const float*)d_in[6],  (const float*)d_in[7],  (const float*)d_in[8],
        (const float*)d_in[9],  (const float*)d_in[10], (const float*)d_in[11],
        (const float*)d_in[12], (const float*)d_in[13], (const float*)d_in[14],
        (const float*)d_in[15], (const float*)d_in[16], (const float*)d_in[17],
        (const float*)d_in[18], (const float*)d_in[19], (const float*)d_in[20]);

    fps_kernel<<<BB, 1024>>>(xyz, seed, out);
    ballq_kernel<<<(BB*SS)/8, 256>>>(xyz);

    static int smem_set = 0;
    (void)smem_set;
    cudaFuncSetAttribute(mlp_kernel, cudaFuncAttributeMaxDynamicSharedMemorySize,
                         SMEM_FLOATS * sizeof(float));
    mlp_kernel<<<BB*256, 256, SMEM_FLOATS * sizeof(float)>>>(xyz, pts, out);
}

// round 4
// speedup vs baseline: 2.1197x; 2.1197x over previous
#include <cuda_runtime.h>
#include <math.h>

#define BB 8
#define NN 8192
#define SS 1024
#define KK 64

// output layout (float32): new_xyz (B,3,S) | new_points (B,128,S) | new_seed (B,S)
#define OUT_XYZ_OFF   0
#define OUT_PTS_OFF   (BB*3*SS)                 // 24576
#define OUT_SEED_OFF  (OUT_PTS_OFF + BB*128*SS) // 1073152

// ---------------- scratch (no allocations allowed) ----------------
__device__ float g_cent[BB*SS*3];
__device__ int   g_gi[BB*SS*KK];
__device__ int   g_cnt[BB*SS];
__device__ float g_w0[64*6],   g_b0[64];
__device__ float g_w1t[64*64], g_b1[64];    // w1t[cc*64 + c] = w1[c][cc] * s1(c)
__device__ float g_w2t[64*128], g_b2[128];  // w2t[cc*128 + o] = w2[o][cc] * s2(o)

// ---------------- f32x2 packed helpers (exact per-lane rn rounding) ----------------
__device__ __forceinline__ unsigned long long f2pack(float lo, float hi) {
    unsigned long long r;
    asm("mov.b64 %0, {%1, %2};" : "=l"(r) : "f"(lo), "f"(hi));
    return r;
}
__device__ __forceinline__ void f2unpack(unsigned long long v, float& lo, float& hi) {
    asm("mov.b64 {%0, %1}, %2;" : "=f"(lo), "=f"(hi) : "l"(v));
}
__device__ __forceinline__ unsigned long long f2add(unsigned long long a, unsigned long long b) {
    unsigned long long d;
    asm("add.rn.f32x2 %0, %1, %2;" : "=l"(d) : "l"(a), "l"(b));
    return d;
}
__device__ __forceinline__ unsigned long long f2mul(unsigned long long a, unsigned long long b) {
    unsigned long long d;
    asm("mul.rn.f32x2 %0, %1, %2;" : "=l"(d) : "l"(a), "l"(b));
    return d;
}

// ---------------- fold BN into weights (+ transpose for mlp) ----------------
__global__ void fold_kernel(
    const float* __restrict__ w0, const float* __restrict__ b0, const float* __restrict__ g0,
    const float* __restrict__ be0, const float* __restrict__ m0, const float* __restrict__ v0,
    const float* __restrict__ w1, const float* __restrict__ b1, const float* __restrict__ g1,
    const float* __restrict__ be1, const float* __restrict__ m1, const float* __restrict__ v1,
    const float* __restrict__ w2, const float* __restrict__ b2, const float* __restrict__ g2,
    const float* __restrict__ be2, const float* __restrict__ m2, const float* __restrict__ v2)
{
    int t = threadIdx.x;
    if (t < 64) {
        float s = g0[t] / sqrtf(v0[t] + 1e-5f);
        g_b0[t] = (b0[t] - m0[t]) * s + be0[t];
        for (int c = 0; c < 6; c++) g_w0[t*6+c] = w0[t*6+c] * s;
    }
    if (t < 64) {
        float s = g1[t] / sqrtf(v1[t] + 1e-5f);
        g_b1[t] = (b1[t] - m1[t]) * s + be1[t];
        for (int cc = 0; cc < 64; cc++) g_w1t[cc*64 + t] = w1[t*64+cc] * s;
    }
    if (t < 128) {
        float s = g2[t] / sqrtf(v2[t] + 1e-5f);
        g_b2[t] = (b2[t] - m2[t]) * s + be2[t];
        for (int cc = 0; cc < 64; cc++) g_w2t[cc*128 + t] = w2[t*64+cc] * s;
    }
}

// ---------------- FPS: one block per batch ----------------
// Distance math uses packed add.rn/mul.rn.f32x2 — per-lane rounding identical to
// scalar __fadd_rn/__fmul_rn in the reference association order ((dx2+dy2)+dz2).
// Argmax via redux on dist bits (dist >= 0 so float order == u32 order);
// ties -> lowest index (lowest lane / lowest warp), matching jnp.argmax.
__global__ __launch_bounds__(1024) void fps_kernel(
    const float* __restrict__ xyz, const int* __restrict__ seed, float* __restrict__ out)
{
    const int b = blockIdx.x;
    const float* xr = xyz + (size_t)b*3*NN;
    const float* yr = xr + NN;
    const float* zr = yr + NN;
    const int tid = threadIdx.x, lane = tid & 31, warp = tid >> 5;
    const int base = tid * 8;

    unsigned long long pxp[4], pyp[4], pzp[4];
    float dist[8];
    {
        const float2* x2 = (const float2*)xr;
        const float2* y2 = (const float2*)yr;
        const float2* z2 = (const float2*)zr;
#pragma unroll
        for (int i = 0; i < 4; i++) {
            float2 vx = x2[tid*4+i], vy = y2[tid*4+i], vz = z2[tid*4+i];
            pxp[i] = f2pack(vx.x, vx.y);
            pyp[i] = f2pack(vy.x, vy.y);
            pzp[i] = f2pack(vz.x, vz.y);
        }
#pragma unroll
        for (int i = 0; i < 8; i++) dist[i] = 1e10f;
    }

    __shared__ unsigned swv[32];
    __shared__ int      swi[32];
    __shared__ int      sfar;
    __shared__ int      sfps[SS];

    int far = 0;
    for (int s = 0; s < SS; s++) {
        if (tid == 0) sfps[s] = far;
        if (s == SS - 1) break;

        float cx = xr[far], cy = yr[far], cz = zr[far];
        unsigned long long ncx2 = f2pack(-cx, -cx);
        unsigned long long ncy2 = f2pack(-cy, -cy);
        unsigned long long ncz2 = f2pack(-cz, -cz);

        float bv = -1.0f; int bi = 0;
#pragma unroll
        for (int i = 0; i < 4; i++) {
            unsigned long long dx = f2add(pxp[i], ncx2);
            unsigned long long dy = f2add(pyp[i], ncy2);
            unsigned long long dz = f2add(pzp[i], ncz2);
            unsigned long long d  = f2add(f2add(f2mul(dx,dx), f2mul(dy,dy)), f2mul(dz,dz));
            float dlo, dhi; f2unpack(d, dlo, dhi);
            float n0 = fminf(dist[2*i],   dlo); dist[2*i]   = n0;
            float n1 = fminf(dist[2*i+1], dhi); dist[2*i+1] = n1;
            if (n0 > bv) { bv = n0; bi = base + 2*i; }
            if (n1 > bv) { bv = n1; bi = base + 2*i + 1; }
        }
        // warp argmax via redux (bv >= 0 for all threads after first point)
        unsigned vb = __float_as_uint(bv);
        unsigned mv = __reduce_max_sync(0xffffffffu, vb);
        unsigned eq = __ballot_sync(0xffffffffu, vb == mv);
        int leader = __ffs(eq) - 1;
        int wbi = __shfl_sync(0xffffffffu, bi, leader);
        if (lane == 0) { swv[warp] = mv; swi[warp] = wbi; }
        __syncthreads();
        if (warp == 0) {
            unsigned v = swv[lane];
            unsigned m2 = __reduce_max_sync(0xffffffffu, v);
            unsigned eq2 = __ballot_sync(0xffffffffu, v == m2);
            int l2 = __ffs(eq2) - 1;
            if (lane == l2) sfar = swi[lane];
        }
        __syncthreads();
        far = sfar;
    }
    __syncthreads();

    {
        int id = sfps[tid];
        float x = xr[id], y = yr[id], z = zr[id];
        out[OUT_XYZ_OFF + (size_t)b*3*SS + 0*SS + tid] = x;
        out[OUT_XYZ_OFF + (size_t)b*3*SS + 1*SS + tid] = y;
        out[OUT_XYZ_OFF + (size_t)b*3*SS + 2*SS + tid] = z;
        out[OUT_SEED_OFF + (size_t)b*SS + tid] = (float)seed[(size_t)b*NN + id];
        g_cent[((size_t)b*SS + tid)*3 + 0] = x;
        g_cent[((size_t)b*SS + tid)*3 + 1] = y;
        g_cent[((size_t)b*SS + tid)*3 + 2] = z;
    }
}

// ---------------- ball query: warp per centroid (unchanged; exact ref math) ----------------
__global__ __launch_bounds__(256) void ballq_kernel(const float* __restrict__ xyz)
{
    const int gw = blockIdx.x * 8 + (threadIdx.x >> 5);
    const int lane = threadIdx.x & 31;
    const int b = gw >> 10;
    const int s = gw & 1023;
    const float* xr = xyz + (size_t)b*3*NN;
    const float* yr = xr + NN;
    const float* zr = yr + NN;

    const float cx = g_cent[((size_t)b*SS+s)*3+0];
    const float cy = g_cent[((size_t)b*SS+s)*3+1];
    const float cz = g_cent[((size_t)b*SS+s)*3+2];
    const float s2 = __fadd_rn(__fadd_rn(__fmul_rn(cx,cx), __fmul_rn(cy,cy)), __fmul_rn(cz,cz));

    __shared__ int sgi[8][KK];
    int* mygi = sgi[threadIdx.x >> 5];

    int cnt = 0;
    for (int j0 = 0; j0 < NN; j0 += 32) {
        int j = j0 + lane;
        float x = xr[j], y = yr[j], z = zr[j];
        float d2  = __fadd_rn(__fadd_rn(__fmul_rn(x,x), __fmul_rn(y,y)), __fmul_rn(z,z));
        float dot = __fadd_rn(__fadd_rn(__fmul_rn(cx,x), __fmul_rn(cy,y)), __fmul_rn(cz,z));
        float sq  = __fadd_rn(__fadd_rn(__fmul_rn(-2.0f, dot), s2), d2);
        bool pred = !(sq > 0.04f);
        unsigned m = __ballot_sync(0xffffffffu, pred);
        int rank = __popc(m & ((1u << lane) - 1u));
        if (pred && (cnt + rank) < KK) mygi[cnt + rank] = j;
        cnt += __popc(m);
        if (cnt >= KK) { cnt = KK; break; }
    }
    __syncwarp();
    if (lane == 0) g_cnt[(size_t)b*SS + s] = cnt;
    for (int k = lane; k < cnt; k += 32)
        g_gi[((size_t)b*SS + s)*KK + k] = mygi[k];
}

// ---------------- fused gather + 3-layer MLP + maxpool ----------------
// One WARP per centroid; loop over the cnt REAL neighbors only (padding
// duplicates can't change the max). Lanes are channel-parallel:
//   layer1/2: lane owns channels c=lane and c=lane+32
//   layer3:   lane owns outputs o=4*lane..4*lane+3
// h1/h2 rows staged in per-warp smem; weights transposed so lane accesses
// are consecutive (conflict-free).
#define MW 4   // warps (centroids) per block
// dynamic smem float offsets
#define O_W1T   0
#define O_W2T   4096
#define O_B1    12288
#define O_B2    12352
#define O_GFT   12480                   // MW * 384
#define O_H1    (O_GFT + MW*384)        // MW * 64
#define O_H2    (O_H1  + MW*64)
#define O_SOUT  (O_H2  + MW*64)         // MW * 128
#define SMEMF   (O_SOUT + MW*128)

__global__ __launch_bounds__(32*MW) void mlp_kernel(
    const float* __restrict__ xyz, const float* __restrict__ pts, float* __restrict__ out)
{
    extern __shared__ float sm[];
    float* sw1t = sm + O_W1T;
    float* sw2t = sm + O_W2T;
    float* sb1  = sm + O_B1;
    float* sb2  = sm + O_B2;

    const int tid = threadIdx.x;
    // cooperative weight load (float4)
    {
        const float4* s1 = (const float4*)g_w1t;
        float4* d1 = (float4*)sw1t;
        for (int i = tid; i < 1024; i += 32*MW) d1[i] = s1[i];
        const float4* s2 = (const float4*)g_w2t;
        float4* d2 = (float4*)sw2t;
        for (int i = tid; i < 2048; i += 32*MW) d2[i] = s2[i];
        for (int i = tid; i < 64; i += 32*MW) sb1[i] = g_b1[i];
        for (int i = tid; i < 128; i += 32*MW) sb2[i] = g_b2[i];
    }
    __syncthreads();

    const int w = tid >> 5;
    const int lane = tid & 31;
    const int gs = blockIdx.x * MW + w;          // global centroid id
    const int b = gs >> 10;
    const int cnt = g_cnt[gs];

    float* gft   = sm + O_GFT + w*384;
    float* h1row = sm + O_H1  + w*64;
    float* h2row = sm + O_H2  + w*64;
    float* sout  = sm + O_SOUT + w*128;

    const float cx = g_cent[(size_t)gs*3+0];
    const float cy = g_cent[(size_t)gs*3+1];
    const float cz = g_cent[(size_t)gs*3+2];

    // gather all neighbor features up front (one latency)
    {
        const int* gi = g_gi + (size_t)gs*KK;
        for (int t = lane; t < cnt*6; t += 32) {
            int k = t / 6, i = t - 6*k;
            int idx = gi[k];
            float v;
            if (i < 3) {
                v = xyz[((size_t)b*3 + i)*NN + idx] - (i==0 ? cx : (i==1 ? cy : cz));
            } else {
                v = pts[((size_t)b*3 + (i-3))*NN + idx];
            }
            gft[t] = v;
        }
    }

    // per-lane constants
    const int cA = lane, cB = lane + 32;
    float w0A[6], w0B[6];
#pragma unroll
    for (int i = 0; i < 6; i++) { w0A[i] = g_w0[cA*6+i]; w0B[i] = g_w0[cB*6+i]; }
    const float b0A = g_b0[cA], b0B = g_b0[cB];
    const float b1A = sb1[cA],  b1B = sb1[cB];
    const float4 b2v = *(const float4*)&sb2[4*lane];

    float m0 = 0.f, m1 = 0.f, m2 = 0.f, m3 = 0.f;
    __syncwarp();

    for (int k = 0; k < cnt; k++) {
        // ---- layer 1 ----
        const float* f = gft + k*6;
        float f0=f[0], f1=f[1], f2=f[2], f3=f[3], f4=f[4], f5=f[5];
        float aA = b0A + w0A[0]*f0 + w0A[1]*f1 + w0A[2]*f2 + w0A[3]*f3 + w0A[4]*f4 + w0A[5]*f5;
        float aB = b0B + w0B[0]*f0 + w0B[1]*f1 + w0B[2]*f2 + w0B[3]*f3 + w0B[4]*f4 + w0B[5]*f5;
        h1row[cA] = fmaxf(aA, 0.f);
        h1row[cB] = fmaxf(aB, 0.f);
        __syncwarp();

        // ---- layer 2 ----
        float pA0 = b1A, pA1 = 0.f, pB0 = b1B, pB1 = 0.f;
        const float4* h1v = (const float4*)h1row;
#pragma unroll
        for (int c4 = 0; c4 < 16; c4++) {
            float4 h = h1v[c4];
            const float* w1r = sw1t + c4*256;
            pA0 += w1r[cA]      * h.x;  pB0 += w1r[cB]      * h.x;
            pA1 += w1r[64+cA]   * h.y;  pB1 += w1r[64+cB]   * h.y;
            pA0 += w1r[128+cA]  * h.z;  pB0 += w1r[128+cB]  * h.z;
            pA1 += w1r[192+cA]  * h.w;  pB1 += w1r[192+cB]  * h.w;
        }
        h2row[cA] = fmaxf(pA0 + pA1, 0.f);
        h2row[cB] = fmaxf(pB0 + pB1, 0.f);
        __syncwarp();

        // ---- layer 3 + running max ----
        float q0=0.f,q1=0.f,q2=0.f,q3=0.f, r0=0.f,r1=0.f,r2=0.f,r3=0.f;
        const float4* h2v = (const float4*)h2row;
#pragma unroll
        for (int c4 = 0; c4 < 16; c4++) {
            float4 h = h2v[c4];
            const float* w2r = sw2t + c4*512;
            float4 wa = *(const float4*)(w2r +        4*lane);
            q0 += wa.x*h.x; q1 += wa.y*h.x; q2 += wa.z*h.x; q3 += wa.w*h.x;
            float4 wb = *(const float4*)(w2r + 128 + 4*lane);
            r0 += wb.x*h.y; r1 += wb.y*h.y; r2 += wb.z*h.y; r3 += wb.w*h.y;
            float4 wc = *(const float4*)(w2r + 256 + 4*lane);
            q0 += wc.x*h.z; q1 += wc.y*h.z; q2 += wc.z*h.z; q3 += wc.w*h.z;
            float4 wd = *(const float4*)(w2r + 384 + 4*lane);
            r0 += wd.x*h.w; r1 += wd.y*h.w; r2 += wd.z*h.w; r3 += wd.w*h.w;
        }
        m0 = fmaxf(m0, fmaxf(b2v.x + q0 + r0, 0.f));
        m1 = fmaxf(m1, fmaxf(b2v.y + q1 + r1, 0.f));
        m2 = fmaxf(m2, fmaxf(b2v.z + q2 + r2, 0.f));
        m3 = fmaxf(m3, fmaxf(b2v.w + q3 + r3, 0.f));
        __syncwarp();
    }

    sout[4*lane+0] = m0;
    sout[4*lane+1] = m1;
    sout[4*lane+2] = m2;
    sout[4*lane+3] = m3;
    __syncthreads();

    // coalesced output: thread tid handles output channel o=tid for the
    // MW consecutive centroids of this block (same batch: 256 blocks/batch).
    {
        int o = tid;  // 0..127
        int bb = blockIdx.x >> 8;
        int s0 = (blockIdx.x & 255) * MW;
        float4 v;
        v.x = sm[O_SOUT + 0*128 + o];
        v.y = sm[O_SOUT + 1*128 + o];
        v.z = sm[O_SOUT + 2*128 + o];
        v.w = sm[O_SOUT + 3*128 + o];
        *(float4*)&out[OUT_PTS_OFF + ((size_t)bb*128 + o)*SS + s0] = v;
    }
}

// ---------------- launch ----------------
extern "C" void kernel_launch(void* const* d_in, const int* in_sizes, int n_in,
                              void* d_out, int out_size)
{
    const float* xyz  = (const float*)d_in[0];
    const float* pts  = (const float*)d_in[1];
    const int*   seed = (const int*)d_in[2];
    float* out = (float*)d_out;

    fold_kernel<<<1, 128>>>(
        (const float*)d_in[3],  (const float*)d_in[4],  (const float*)d_in[5],
        (const float*)d_in[6],  (const float*)d_in[7],  (const float*)d_in[8],
        (const float*)d_in[9],  (const float*)d_in[10], (const float*)d_in[11],
        (const float*)d_in[12], (const float*)d_in[13], (const float*)d_in[14],
        (const float*)d_in[15], (const float*)d_in[16], (const float*)d_in[17],
        (const float*)d_in[18], (const float*)d_in[19], (const float*)d_in[20]);

    fps_kernel<<<BB, 1024>>>(xyz, seed, out);
    ballq_kernel<<<(BB*SS)/8, 256>>>(xyz);

    cudaFuncSetAttribute(mlp_kernel, cudaFuncAttributeMaxDynamicSharedMemorySize,
                         SMEMF * sizeof(float));
    mlp_kernel<<<(BB*SS)/MW, 32*MW, SMEMF * sizeof(float)>>>(xyz, pts, out);
}